// round 17
// baseline (speedup 1.0000x reference)
#include <cuda_runtime.h>

#define BB   64
#define TT   512
#define HH   1024
#define CC   8
#define NROW 32768
#define NLOG (3 * NROW * CC)
#define LOGITS_OFF 1
#define PRED_OFF   (1 + 3*BB*TT*CC)
#define FULLM 0xFFFFFFFFu

__device__ float g_expo[NLOG];    // exp(logits)
__device__ int   g_flag[256];     // gemm row-block completion flags

__device__ __forceinline__ void cpa16(unsigned sm, const void* g) {
    asm volatile("cp.async.cg.shared.global [%0], [%1], 16;" :: "r"(sm), "l"(g));
}
__device__ __forceinline__ unsigned tf32c(float x) {
    unsigned r;
    asm("cvt.rna.tf32.f32 %0, %1;" : "=r"(r) : "f"(x));
    return r;
}
__device__ __forceinline__ void mma8(float* c,
    unsigned a0, unsigned a1, unsigned a2, unsigned a3,
    unsigned b0, unsigned b1)
{
    asm("mma.sync.aligned.m16n8k8.row.col.f32.tf32.tf32.f32 "
        "{%0,%1,%2,%3},{%4,%5,%6,%7},{%8,%9},{%0,%1,%2,%3};"
        : "+f"(c[0]), "+f"(c[1]), "+f"(c[2]), "+f"(c[3])
        : "r"(a0), "r"(a1), "r"(a2), "r"(a3), "r"(b0), "r"(b1));
}

// shared-memory union (max branch ~41.3KB < 48KB static limit)
struct GemmSm {
    float As[3][128 * 20];
    float Ws[3][24 * 20];
};
struct ChainSm {
    float         vsm[2][TT][8];
    unsigned char path[2][8][8][64];
    unsigned char sel[2][8];
    float         strT[64];
    int           lastsh[2];
};
struct MatSm {
    float Psm[2][8][8][8];
    float numsh[2];
};
#define SMRAW_BYTES 41472

__global__ void init_kernel() { g_flag[threadIdx.x] = 0; }

// ---------------------------------------------------------------------------
// fused kernel: 448 blocks x 160 threads
//   bids 0..255   : tf32 gemm row-block (128 rows) -> logits+expo, set flag
//   bids 256..351 : viterbi chain + decode for seqs {2g, 2g+1}
//   bids 352..447 : forward matrices + numerator + logZ + loss
// ---------------------------------------------------------------------------
__global__ __launch_bounds__(160, 2) void fused_kernel(
    const float* __restrict__ enc, const float* __restrict__ W,
    const float* __restrict__ bias, const int* __restrict__ labels,
    const float* __restrict__ start_t, const float* __restrict__ end_t,
    const float* __restrict__ trans, float* __restrict__ out)
{
    __shared__ alignas(16) unsigned char smraw[SMRAW_BYTES];
    const int tid  = threadIdx.x;
    const int lane = tid & 31;

    if (blockIdx.x < 256) {
        // ========================= GEMM block =========================
        GemmSm* gs = reinterpret_cast<GemmSm*>(smraw);
        const int wid = tid >> 5;
        const int g   = lane >> 2;
        const int tg  = lane & 3;
        const int rb  = blockIdx.x * 128;
        if (blockIdx.x == 0 && tid == 0) out[0] = 0.0f;

        float acc[2][3][4];
        #pragma unroll
        for (int mt = 0; mt < 2; mt++)
            #pragma unroll
            for (int nt = 0; nt < 3; nt++)
                #pragma unroll
                for (int q = 0; q < 4; q++) acc[mt][nt][q] = 0.0f;

        unsigned asB[3] = { (unsigned)__cvta_generic_to_shared(&gs->As[0][0]),
                            (unsigned)__cvta_generic_to_shared(&gs->As[1][0]),
                            (unsigned)__cvta_generic_to_shared(&gs->As[2][0]) };
        unsigned wsB[3] = { (unsigned)__cvta_generic_to_shared(&gs->Ws[0][0]),
                            (unsigned)__cvta_generic_to_shared(&gs->Ws[1][0]),
                            (unsigned)__cvta_generic_to_shared(&gs->Ws[2][0]) };

        auto load_tiles = [&](int kb, int bf) {
            if (tid < 128) {
                #pragma unroll
                for (int i = 0; i < 4; i++) {
                    int idx = tid + i * 128;
                    int row = idx >> 2, q = idx & 3;
                    cpa16(asB[bf] + (row * 20 + q * 4) * 4,
                          enc + (size_t)(rb + row) * HH + kb + q * 4);
                }
            } else {
                #pragma unroll
                for (int i = 0; i < 3; i++) {
                    int idx = (tid - 128) + i * 32;   // 0..95
                    int c = idx >> 2, q = idx & 3;
                    cpa16(wsB[bf] + (c * 20 + q * 4) * 4,
                          W + (size_t)c * HH + kb + q * 4);
                }
            }
            asm volatile("cp.async.commit_group;");
        };

        load_tiles(0, 0);
        load_tiles(16, 1);
        int buf = 0;
        for (int kb = 0; kb < HH; kb += 16) {
            if (kb + 32 < HH) {
                load_tiles(kb + 32, (buf + 2) % 3);
                asm volatile("cp.async.wait_group 2;");
            } else if (kb + 16 < HH) {
                asm volatile("cp.async.wait_group 1;");
            } else {
                asm volatile("cp.async.wait_group 0;");
            }
            __syncthreads();

            if (tid < 128) {
                #pragma unroll
                for (int k8 = 0; k8 < 16; k8 += 8) {
                    unsigned bb[3][2], bs[3][2];
                    #pragma unroll
                    for (int nt = 0; nt < 3; nt++) {
                        float b0f = gs->Ws[buf][(nt * 8 + g) * 20 + k8 + tg];
                        float b1f = gs->Ws[buf][(nt * 8 + g) * 20 + k8 + tg + 4];
                        bb[nt][0] = tf32c(b0f);
                        bb[nt][1] = tf32c(b1f);
                        bs[nt][0] = tf32c(b0f - __uint_as_float(bb[nt][0]));
                        bs[nt][1] = tf32c(b1f - __uint_as_float(bb[nt][1]));
                    }
                    #pragma unroll
                    for (int mt = 0; mt < 2; mt++) {
                        int row0 = (wid * 2 + mt) * 16 + g;
                        float a0f = gs->As[buf][row0 * 20 + k8 + tg];
                        float a1f = gs->As[buf][(row0 + 8) * 20 + k8 + tg];
                        float a2f = gs->As[buf][row0 * 20 + k8 + tg + 4];
                        float a3f = gs->As[buf][(row0 + 8) * 20 + k8 + tg + 4];
                        unsigned ab0 = tf32c(a0f), ab1 = tf32c(a1f);
                        unsigned ab2 = tf32c(a2f), ab3 = tf32c(a3f);
                        unsigned as0 = tf32c(a0f - __uint_as_float(ab0));
                        unsigned as1 = tf32c(a1f - __uint_as_float(ab1));
                        unsigned as2 = tf32c(a2f - __uint_as_float(ab2));
                        unsigned as3 = tf32c(a3f - __uint_as_float(ab3));
                        #pragma unroll
                        for (int nt = 0; nt < 3; nt++) {
                            mma8(acc[mt][nt], as0, as1, as2, as3, bb[nt][0], bb[nt][1]);
                            mma8(acc[mt][nt], ab0, ab1, ab2, ab3, bs[nt][0], bs[nt][1]);
                            mma8(acc[mt][nt], ab0, ab1, ab2, ab3, bb[nt][0], bb[nt][1]);
                        }
                    }
                }
            }
            __syncthreads();
            buf = (buf + 1) % 3;
        }

        if (tid < 128) {
            #pragma unroll
            for (int mt = 0; mt < 2; mt++) {
                const int r0 = rb + (wid * 2 + mt) * 16 + g;
                #pragma unroll
                for (int nt = 0; nt < 3; nt++) {
                    const int col0 = nt * 8 + 2 * tg;
                    const int kt = col0 >> 3, cc = col0 & 7;
                    float v0 = acc[mt][nt][0] + bias[col0];
                    float v1 = acc[mt][nt][1] + bias[col0 + 1];
                    float v2 = acc[mt][nt][2] + bias[col0];
                    float v3 = acc[mt][nt][3] + bias[col0 + 1];
                    size_t b0 = ((size_t)kt * NROW + r0) * 8 + cc;
                    size_t b2 = ((size_t)kt * NROW + r0 + 8) * 8 + cc;
                    out[LOGITS_OFF + b0]     = v0;
                    out[LOGITS_OFF + b0 + 1] = v1;
                    out[LOGITS_OFF + b2]     = v2;
                    out[LOGITS_OFF + b2 + 1] = v3;
                    float2 e0 = { __expf(v0), __expf(v1) };
                    float2 e2 = { __expf(v2), __expf(v3) };
                    *reinterpret_cast<float2*>(&g_expo[b0]) = e0;
                    *reinterpret_cast<float2*>(&g_expo[b2]) = e2;
                }
            }
        }
        __threadfence();
        __syncthreads();
        if (tid == 0) atomicExch(&g_flag[blockIdx.x], 1);

    } else if (blockIdx.x < 352) {
        // ==================== chain + decode block ====================
        ChainSm* cs = reinterpret_cast<ChainSm*>(smraw);
        const int gblk = blockIdx.x - 256;       // 0..95
        const int s0 = gblk * 2;
        const int kt = s0 >> 6;
        const int b0 = s0 & 63;                  // even

        if (tid == 0) {
            const int base = 4 * b0;
            #pragma unroll
            for (int i = 0; i < 8; i++)
                while (((volatile int*)g_flag)[base + i] == 0) __nanosleep(64);
        }
        __syncthreads();
        __threadfence();

        if (tid < 64) cs->strT[tid] = trans[kt * 64 + (tid & 7) * 8 + (tid >> 3)];

        if (tid < 32) {
            const int sl    = (lane >> 3) & 1;
            const int j     = lane & 7;
            const int rbase = (lane >> 4) * 4;
            const int s     = s0 + sl;
            const float* em = out + LOGITS_OFF + (size_t)s * (TT * CC);

            float tr[4];
            #pragma unroll
            for (int r = 0; r < 4; r++) tr[r] = trans[kt * 64 + (rbase + r) * 8 + j];

            float v = start_t[kt * 8 + j] + em[j];
            if (lane < 16) cs->vsm[sl][0][j] = v;

            float eb[8];
            #pragma unroll
            for (int u = 0; u < 8; u++) eb[u] = em[(1 + u) * 8 + j];

            for (int tw = 1; tw < TT - 14; tw += 8) {
                float nb[8];
                #pragma unroll
                for (int u = 0; u < 8; u++) nb[u] = em[(tw + 8 + u) * 8 + j];
                #pragma unroll
                for (int u = 0; u < 8; u++) {
                    const int t = tw + u;
                    float c0 = __shfl_sync(FULLM, v, rbase + 0, 8) + tr[0];
                    float c1 = __shfl_sync(FULLM, v, rbase + 1, 8) + tr[1];
                    float c2 = __shfl_sync(FULLM, v, rbase + 2, 8) + tr[2];
                    float c3 = __shfl_sync(FULLM, v, rbase + 3, 8) + tr[3];
                    float pm = fmaxf(fmaxf(c0, c1), fmaxf(c2, c3));
                    float om = __shfl_xor_sync(FULLM, pm, 16, 32);
                    float m  = fmaxf(pm, om);
                    v = m + eb[u];
                    if (lane < 16) cs->vsm[sl][t][j] = v;
                }
                #pragma unroll
                for (int u = 0; u < 8; u++) eb[u] = nb[u];
            }
            #pragma unroll
            for (int u = 0; u < 7; u++) {
                const int t = (TT - 7) + u;
                float c0 = __shfl_sync(FULLM, v, rbase + 0, 8) + tr[0];
                float c1 = __shfl_sync(FULLM, v, rbase + 1, 8) + tr[1];
                float c2 = __shfl_sync(FULLM, v, rbase + 2, 8) + tr[2];
                float c3 = __shfl_sync(FULLM, v, rbase + 3, 8) + tr[3];
                float pm = fmaxf(fmaxf(c0, c1), fmaxf(c2, c3));
                float om = __shfl_xor_sync(FULLM, pm, 16, 32);
                float m  = fmaxf(pm, om);
                v = m + eb[u];
                if (lane < 16) cs->vsm[sl][t][j] = v;
            }

            float y = v + end_t[kt * 8 + j];
            float gg[8];
            #pragma unroll
            for (int i = 0; i < 8; i++) gg[i] = __shfl_sync(FULLM, y, i, 8);
            float bv = gg[0]; int last = 0;
            #pragma unroll
            for (int i = 1; i < 8; i++) { if (gg[i] > bv) { bv = gg[i]; last = i; } }
            if (lane < 16 && j == 0) cs->lastsh[sl] = last;
        }
        __syncthreads();

        if (tid >= 32) {
            const int did   = tid - 32;
            const int local = did >> 6;
            const int lt    = did & 63;
            const int c  = lt >> 3, h = lt & 7;
            const int tb = c * 64 + 1;
            const int te = (c * 64 + 64 < TT) ? c * 64 + 64 : TT - 1;
            int tag = h;
            for (int t = te; t >= tb; t--) {
                float4 va = *reinterpret_cast<const float4*>(&cs->vsm[local][t - 1][0]);
                float4 vb = *reinterpret_cast<const float4*>(&cs->vsm[local][t - 1][4]);
                const float* tc = &cs->strT[tag * 8];
                float c0 = va.x + tc[0], c1 = va.y + tc[1];
                float c2 = va.z + tc[2], c3 = va.w + tc[3];
                float c4 = vb.x + tc[4], c5 = vb.y + tc[5];
                float c6 = vb.z + tc[6], c7 = vb.w + tc[7];
                float m = fmaxf(fmaxf(fmaxf(c0, c1), fmaxf(c2, c3)),
                                fmaxf(fmaxf(c4, c5), fmaxf(c6, c7)));
                unsigned mk = (c0 == m) ? 1u : 0u;
                mk |= (c1 == m) ? 2u : 0u;
                mk |= (c2 == m) ? 4u : 0u;
                mk |= (c3 == m) ? 8u : 0u;
                mk |= (c4 == m) ? 16u : 0u;
                mk |= (c5 == m) ? 32u : 0u;
                mk |= (c6 == m) ? 64u : 0u;
                mk |= (c7 == m) ? 128u : 0u;
                tag = __ffs(mk) - 1;
                cs->path[local][c][h][t - tb] = (unsigned char)tag;
            }
        }
        __syncthreads();

        if (tid == 32 || tid == 96) {
            const int local = (tid - 32) >> 6;
            int ex = cs->lastsh[local];
            for (int cc = 7; cc >= 0; cc--) {
                cs->sel[local][cc] = (unsigned char)ex;
                ex = cs->path[local][cc][ex][0];
            }
        }
        __syncthreads();

        if (tid >= 32) {
            const int did   = tid - 32;
            const int local = did >> 6;
            const int lt    = did & 63;
            if (lt < 8) {
                const int cc = lt;
                const int tb = cc * 64 + 1;
                const int te = (cc * 64 + 64 < TT) ? cc * 64 + 64 : TT - 1;
                const int stag = cs->sel[local][cc];
                float* pred = out + PRED_OFF + (size_t)(s0 + local) * TT;
                pred[te] = (float)stag;
                const unsigned char* pp = &cs->path[local][cc][stag][0];
                for (int idx = te - tb; idx >= 0; idx--)
                    pred[tb - 1 + idx] = (float)pp[idx];
            }
        }
    } else {
        // ============ matrices + numerator + logZ + loss ============
        MatSm* ms = reinterpret_cast<MatSm*>(smraw);
        const int gblk = blockIdx.x - 352;       // 0..95
        const int s0 = gblk * 2;
        const int kt = s0 >> 6;
        const int b0 = s0 & 63;

        if (tid == 0) {
            const int base = 4 * b0;
            #pragma unroll
            for (int i = 0; i < 8; i++)
                while (((volatile int*)g_flag)[base + i] == 0) __nanosleep(64);
            while (((volatile int*)g_flag)[0] == 0) __nanosleep(64);  // out[0] init
        }
        __syncthreads();
        __threadfence();

        if (tid < 128) {
            const int ib = tid & 7;
            const int c  = (tid >> 3) & 7;
            const int sl = tid >> 6;
            const int s  = s0 + sl;

            float ec[64];
            #pragma unroll
            for (int i = 0; i < 64; i++) ec[i] = __expf(trans[kt * 64 + i]) * 0.125f;

            float P[8];
            #pragma unroll
            for (int jj = 0; jj < 8; jj++) P[jj] = (jj == ib) ? 1.0f : 0.0f;

            const int tb = c * 64 + 1;
            const int te = (c * 64 + 64 < TT) ? c * 64 + 64 : TT - 1;
            const float* eo = g_expo + (size_t)s * (TT * CC);

            float4 pa0 = *reinterpret_cast<const float4*>(eo + tb * 8);
            float4 pb0 = *reinterpret_cast<const float4*>(eo + tb * 8 + 4);
            float4 pa1 = *reinterpret_cast<const float4*>(eo + (tb + 1) * 8);
            float4 pb1 = *reinterpret_cast<const float4*>(eo + (tb + 1) * 8 + 4);

            for (int t = tb; t <= te; t++) {
                float4 ca = pa0, cb = pb0;
                pa0 = pa1; pb0 = pb1;
                int tn = t + 2;
                if (tn <= te) {
                    pa1 = *reinterpret_cast<const float4*>(eo + tn * 8);
                    pb1 = *reinterpret_cast<const float4*>(eo + tn * 8 + 4);
                }
                float np[8];
                #pragma unroll
                for (int jj = 0; jj < 8; jj++) {
                    float sum = P[0] * ec[jj];
                    #pragma unroll
                    for (int i = 1; i < 8; i++) sum = fmaf(P[i], ec[i * 8 + jj], sum);
                    np[jj] = sum;
                }
                P[0] = np[0] * ca.x; P[1] = np[1] * ca.y;
                P[2] = np[2] * ca.z; P[3] = np[3] * ca.w;
                P[4] = np[4] * cb.x; P[5] = np[5] * cb.y;
                P[6] = np[6] * cb.z; P[7] = np[7] * cb.w;
            }
            #pragma unroll
            for (int jj = 0; jj < 8; jj++) ms->Psm[sl][c][ib][jj] = P[jj];
        } else {
            const int nid = tid - 128;
            if (nid < 16) {
                const int sl = nid >> 3, j = nid & 7;
                const int s  = s0 + sl, b = s & 63;
                const float* em = out + LOGITS_OFF + (size_t)s * (TT * CC);
                const int* lab = labels + b * (3 * TT) + kt * TT;
                float num = 0.0f;
                for (int u0 = 0; u0 < 64; u0 += 4) {
                    int tg[4], tp[4];
                    #pragma unroll
                    for (int u = 0; u < 4; u++) {
                        int t = j + 8 * (u0 + u);
                        tg[u] = lab[t];
                        tp[u] = (t > 0) ? lab[t - 1] : 0;
                    }
                    #pragma unroll
                    for (int u = 0; u < 4; u++) {
                        int t = j + 8 * (u0 + u);
                        num += em[t * 8 + tg[u]];
                        num += (t > 0) ? trans[kt * 64 + tp[u] * 8 + tg[u]]
                                       : start_t[kt * 8 + tg[u]];
                        if (t == TT - 1) num += end_t[kt * 8 + tg[u]];
                    }
                }
                #pragma unroll
                for (int d = 4; d > 0; d >>= 1) num += __shfl_xor_sync(0xFFFFu, num, d, 8);
                if (j == 0) ms->numsh[sl] = num;
            }
        }
        __syncthreads();

        if (tid < 16) {
            const int sl = tid >> 3, j = tid & 7;
            const int s  = s0 + sl;
            const float* em = out + LOGITS_OFF + (size_t)s * (TT * CC);
            const float LOG8 = 2.0794415416798357f;

            float a = start_t[kt * 8 + j] + em[j];
            for (int c = 0; c < 8; c++) {
                float n = (c < 7) ? 64.0f : 63.0f;
                float lm[8];
                #pragma unroll
                for (int i = 0; i < 8; i++)
                    lm[i] = __logf(ms->Psm[sl][c][i][j]) + n * LOG8 + __shfl_sync(0xFFFFu, a, i, 8);
                float m = fmaxf(fmaxf(fmaxf(lm[0], lm[1]), fmaxf(lm[2], lm[3])),
                                fmaxf(fmaxf(lm[4], lm[5]), fmaxf(lm[6], lm[7])));
                float ssum = 0.0f;
                #pragma unroll
                for (int i = 0; i < 8; i++) ssum += __expf(lm[i] - m);
                a = m + __logf(ssum);
            }
            float y = a + end_t[kt * 8 + j];
            float mm = y;
            #pragma unroll
            for (int d = 4; d > 0; d >>= 1) mm = fmaxf(mm, __shfl_xor_sync(0xFFFFu, mm, d, 8));
            float q = __expf(y - mm);
            #pragma unroll
            for (int d = 4; d > 0; d >>= 1) q += __shfl_xor_sync(0xFFFFu, q, d, 8);
            float logZ = mm + __logf(q);
            if (j == 0) atomicAdd(&out[0], logZ - ms->numsh[sl]);
        }
    }
}

extern "C" void kernel_launch(void* const* d_in, const int* in_sizes, int n_in,
                              void* d_out, int out_size)
{
    (void)in_sizes; (void)n_in; (void)out_size;
    const float* enc     = (const float*)d_in[0];
    const int*   labels  = (const int*)  d_in[1];
    const float* W       = (const float*)d_in[2];
    const float* bias    = (const float*)d_in[3];
    const float* start_t = (const float*)d_in[4];
    const float* end_t   = (const float*)d_in[5];
    const float* trans   = (const float*)d_in[6];
    float* out = (float*)d_out;

    init_kernel <<<1, 256>>>();
    fused_kernel<<<448, 160>>>(enc, W, bias, labels, start_t, end_t, trans, out);
}